// round 6
// baseline (speedup 1.0000x reference)
#include <cuda_runtime.h>
#include <cstdint>

#define B_   32
#define G_   2704
#define D_   1024
#define L_   20
#define HID_ 512
#define K_   128
#define OUTROWS (K_ + L_)     // 148
#define BOXSTRIDE 18          // A*C = 3*6

// ---------------- scratch (no allocations allowed) ----------------
__device__ int   g_sel_by_rank[B_ * K_];
__device__ int   g_idx[B_ * K_];
__device__ float g_gathered[B_ * K_ * D_];   // 16.8 MB, [B*K, D] row-major

// monotone float->uint mapping
__device__ __forceinline__ unsigned int ord32(float f) {
    unsigned int u = __float_as_uint(f);
    return (u & 0x80000000u) ? ~u : (u | 0x80000000u);
}

// ---------------------------------------------------------------------------
// Kernel 1: per-batch scores -> exact top-K via rank counting.
// key = (ord(score) << 32) | (G - g): bigger score wins; equal score -> lower
// g wins (matches jax.lax.top_k tie-break). Rank r = #{keys > mine}; the K
// selected elements have unique ranks 0..K-1 -> scatter by rank.
// grid = (B, 6), block = 512.
// ---------------------------------------------------------------------------
__global__ void __launch_bounds__(512) topk_kernel(const float* __restrict__ boxes) {
    __shared__ __align__(16) unsigned long long keys[G_];
    int b    = blockIdx.x;
    int tid  = threadIdx.x;
    const float* bb = boxes + (size_t)b * G_ * BOXSTRIDE;

    for (int g = tid; g < G_; g += 512) {
        int base = g * BOXSTRIDE;
        float sc = (bb[base + 4] + bb[base + 10] + bb[base + 16]) * (1.0f / 3.0f);
        keys[g] = ((unsigned long long)ord32(sc) << 32) | (unsigned int)(G_ - g);
    }
    __syncthreads();

    int q = blockIdx.y * 512 + tid;
    if (q < G_) {
        unsigned long long my = keys[q];
        int cnt = 0;
        #pragma unroll 4
        for (int j = 0; j < G_ / 2; j++) {
            ulonglong2 kv = *(const ulonglong2*)&keys[2 * j];
            cnt += (kv.x > my);
            cnt += (kv.y > my);
        }
        if (cnt < K_) g_sel_by_rank[b * K_ + cnt] = q;
    }
}

// ---------------------------------------------------------------------------
// Kernel 2: re-order the K selected grid indices ascending (torch mask order),
// write g_idx, and emit sel_boxes (18 contiguous floats per selection).
// grid = B, block = K.
// ---------------------------------------------------------------------------
__global__ void __launch_bounds__(K_) order_kernel(const float* __restrict__ boxes,
                                                   float* __restrict__ out_boxes) {
    __shared__ int gs[K_];
    int b = blockIdx.x, t = threadIdx.x;
    int g = g_sel_by_rank[b * K_ + t];
    gs[t] = g;
    __syncthreads();
    int pos = 0;
    #pragma unroll 8
    for (int j = 0; j < K_; j++) pos += (gs[j] < g);
    g_idx[b * K_ + pos] = g;

    const float* src = boxes + ((size_t)b * G_ + g) * BOXSTRIDE;
    float*       dst = out_boxes + ((size_t)b * K_ + pos) * BOXSTRIDE;
    #pragma unroll
    for (int c = 0; c < BOXSTRIDE; c++) dst[c] = src[c];
}

// ---------------------------------------------------------------------------
// Kernel 3: gather selected feature columns into contiguous [B*K, D].
// Reads are stride-G (sector-wasteful but one-time ~134MB); writes coalesced.
// grid = B*K*D/256, block = 256.
// ---------------------------------------------------------------------------
__global__ void __launch_bounds__(256) gather_kernel(const float* __restrict__ feature) {
    int i = blockIdx.x * 256 + threadIdx.x;
    int d = i & (D_ - 1);
    int k = (i >> 10) & (K_ - 1);
    int b = i >> 17;
    int g = g_idx[b * K_ + k];
    g_gathered[i] = __ldg(&feature[((size_t)(b * D_ + d)) * G_ + g]);
}

// ---------------------------------------------------------------------------
// Kernel 4: fp32 GEMM out[m,n] = sum_d A[m,d]*W[d,n] + bias[n], using packed
// fma.rn.f32x2 (pairs along M: A pairs load directly from SMEM as LDS.64,
// only the B operand needs a mov.b64 {r,r} duplicate). 128x64x16 tiles,
// 256 threads, 8x4 per-thread microtile. DOUBLE-BUFFERED smem: one barrier
// per k-tile; STS of tile k+1 interleaves with FFMA2 stream of tile k.
// Row m maps to output row (m/rowsPerBatch)*148 + rowOffset + m%rowsPerBatch.
// Am == nullptr selects the gathered-feature scratch as A.
// ---------------------------------------------------------------------------
#define BM 128
#define BN 64
#define BKD 16
#define ASTR (BM + 4)   // pad kills STS bank conflicts, keeps 16B align

__global__ void __launch_bounds__(256) gemm_kernel(
    const float* __restrict__ Am, const float* __restrict__ Wm,
    const float* __restrict__ bias, float* __restrict__ out,
    int Kd, int rowsPerBatch, int rowOffset)
{
    if (Am == nullptr) Am = g_gathered;

    __shared__ __align__(16) float As[2][BKD][ASTR];
    __shared__ __align__(16) float Bs[2][BKD][BN];

    int tid   = threadIdx.x;
    int mTile = blockIdx.y * BM;
    int nTile = blockIdx.x * BN;

    int tx = tid & 15, ty = tid >> 4;
    int m0 = ty * 8,   n0 = tx * 4;

    // load-phase mapping
    int ar = tid >> 2;            // 0..63 (rows ar and ar+64)
    int ac = (tid & 3) * 4;       // 0,4,8,12
    int br = tid >> 4;            // 0..15
    int bc = (tid & 15) * 4;      // 0..60

    const float* Aptr0 = Am + (size_t)(mTile + ar)      * Kd + ac;
    const float* Aptr1 = Am + (size_t)(mTile + ar + 64) * Kd + ac;
    const float* Bptr  = Wm + (size_t)br * HID_ + nTile + bc;

    unsigned long long acc[4][4];
    #pragma unroll
    for (int i = 0; i < 4; i++)
        #pragma unroll
        for (int j = 0; j < 4; j++) acc[i][j] = 0ULL;

    int nk = Kd / BKD;

    // prologue: fill buffer 0
    float4 a0 = *(const float4*)(Aptr0);
    float4 a1 = *(const float4*)(Aptr1);
    float4 bv = *(const float4*)(Bptr);
    As[0][ac + 0][ar]      = a0.x; As[0][ac + 1][ar]      = a0.y;
    As[0][ac + 2][ar]      = a0.z; As[0][ac + 3][ar]      = a0.w;
    As[0][ac + 0][ar + 64] = a1.x; As[0][ac + 1][ar + 64] = a1.y;
    As[0][ac + 2][ar + 64] = a1.z; As[0][ac + 3][ar + 64] = a1.w;
    *(float4*)&Bs[0][br][bc] = bv;
    __syncthreads();

    for (int kb = 0; kb < nk; kb++) {
        int cur = kb & 1, nxt = cur ^ 1;
        bool more = (kb + 1 < nk);

        if (more) {   // global prefetch for tile kb+1 (issues early, drains under compute)
            a0 = *(const float4*)(Aptr0 + (kb + 1) * BKD);
            a1 = *(const float4*)(Aptr1 + (kb + 1) * BKD);
            bv = *(const float4*)(Bptr + (size_t)(kb + 1) * BKD * HID_);
        }

        #pragma unroll
        for (int kk = 0; kk < BKD; kk++) {
            ulonglong2 ap0 = *(const ulonglong2*)&As[cur][kk][m0];
            ulonglong2 ap1 = *(const ulonglong2*)&As[cur][kk][m0 + 4];
            unsigned long long a2[4] = {ap0.x, ap0.y, ap1.x, ap1.y};
            float4 bq = *(const float4*)&Bs[cur][kk][n0];
            unsigned long long b2[4];
            asm("mov.b64 %0, {%1,%1};" : "=l"(b2[0]) : "r"(__float_as_uint(bq.x)));
            asm("mov.b64 %0, {%1,%1};" : "=l"(b2[1]) : "r"(__float_as_uint(bq.y)));
            asm("mov.b64 %0, {%1,%1};" : "=l"(b2[2]) : "r"(__float_as_uint(bq.z)));
            asm("mov.b64 %0, {%1,%1};" : "=l"(b2[3]) : "r"(__float_as_uint(bq.w)));
            #pragma unroll
            for (int i = 0; i < 4; i++)
                #pragma unroll
                for (int j = 0; j < 4; j++)
                    asm("fma.rn.f32x2 %0, %1, %2, %0;"
                        : "+l"(acc[i][j]) : "l"(a2[i]), "l"(b2[j]));
        }

        if (more) {   // STS into the other buffer, overlapped with tail of compute
            As[nxt][ac + 0][ar]      = a0.x; As[nxt][ac + 1][ar]      = a0.y;
            As[nxt][ac + 2][ar]      = a0.z; As[nxt][ac + 3][ar]      = a0.w;
            As[nxt][ac + 0][ar + 64] = a1.x; As[nxt][ac + 1][ar + 64] = a1.y;
            As[nxt][ac + 2][ar + 64] = a1.z; As[nxt][ac + 3][ar + 64] = a1.w;
            *(float4*)&Bs[nxt][br][bc] = bv;
        }
        __syncthreads();
    }

    float4 bias4 = *(const float4*)&bias[nTile + n0];
    #pragma unroll
    for (int i = 0; i < 4; i++) {
        float2 v[4];
        #pragma unroll
        for (int j = 0; j < 4; j++) v[j] = *(float2*)&acc[i][j];

        int m    = mTile + m0 + 2 * i;        // even row of the pair
        int bat  = m / rowsPerBatch;
        int r    = m - bat * rowsPerBatch;
        float* o0 = out + (size_t)bat * (OUTROWS * HID_)
                        + (size_t)(rowOffset + r) * HID_ + nTile + n0;
        *(float4*)o0 = make_float4(v[0].x + bias4.x, v[1].x + bias4.y,
                                   v[2].x + bias4.z, v[3].x + bias4.w);

        int m1   = m + 1;
        int bat1 = m1 / rowsPerBatch;
        int r1   = m1 - bat1 * rowsPerBatch;
        float* o1 = out + (size_t)bat1 * (OUTROWS * HID_)
                        + (size_t)(rowOffset + r1) * HID_ + nTile + n0;
        *(float4*)o1 = make_float4(v[0].y + bias4.x, v[1].y + bias4.y,
                                   v[2].y + bias4.z, v[3].y + bias4.w);
    }
}

// ---------------------------------------------------------------------------
// Launch: out = [ concat(linear_feature, linear_text) : B x 148 x 512,
//                 sel_boxes : B x 128 x 3 x 6 ]  (tuple order, flattened)
// ---------------------------------------------------------------------------
extern "C" void kernel_launch(void* const* d_in, const int* in_sizes, int n_in,
                              void* d_out, int out_size) {
    const float* boxes   = (const float*)d_in[0];
    const float* feature = (const float*)d_in[1];
    const float* text    = (const float*)d_in[2];
    const float* W_vs    = (const float*)d_in[3];
    const float* b_vs    = (const float*)d_in[4];
    const float* W_tx    = (const float*)d_in[5];
    const float* b_tx    = (const float*)d_in[6];
    (void)in_sizes; (void)n_in; (void)out_size;

    float* out       = (float*)d_out;
    float* out_boxes = out + (size_t)B_ * OUTROWS * HID_;

    topk_kernel <<<dim3(B_, 6), 512>>>(boxes);
    order_kernel<<<B_, K_>>>(boxes, out_boxes);
    gather_kernel<<<(B_ * K_ * D_) / 256, 256>>>(feature);

    // linear_feature: [B*K, 1024] @ [1024, 512] -> rows 0..127 of each batch
    gemm_kernel<<<dim3(HID_ / BN, (B_ * K_) / BM), 256>>>(
        nullptr, W_vs, b_vs, out, D_, K_, 0);

    // linear_text: [B*L, 512] @ [512, 512] -> rows 128..147 of each batch
    gemm_kernel<<<dim3(HID_ / BN, (B_ * L_) / BM), 256>>>(
        text, W_tx, b_tx, out, HID_, L_, K_);
}